// round 8
// baseline (speedup 1.0000x reference)
#include <cuda_runtime.h>
#include <cuda_fp16.h>
#include <stdint.h>

// Problem constants
#define TT   256
#define BB   128
#define NIN  784
#define NHID 512
#define NOUT 128
#define MM   (TT*BB)        // 32768 (t,b) pairs
#define KPAD 832            // 784 padded to 13*64
#define NCH  13             // gemm1 K chunks of 64
#define NCH2 8              // gemm2 K chunks of 64 (512/64)
#define MTILES (MM/128)     // 256
#define G1GRID 304          // 2 CTAs/SM x 152 SMs (GB300)

// CUBA constants (exactly fp32-rounded like JAX)
#define C_A ((float)(1e-6*(1.0/6e-6)))           // 0.16666667f
#define C_D ((float)(1.0 - 1e-6*(1.0/6e-6)))     // 0.8333333f

// ---- scratch (device globals; no allocations allowed) ----
__device__ __half   g_a16 [(size_t)MM*KPAD];   // spikes fp16 K-padded    54.5 MB
__device__ __half   g_bhi [NHID*KPAD];         // w_hidden hi fp16        0.85 MB
__device__ __half   g_blo [NHID*KPAD];         // w_hidden lo fp16        0.85 MB
__device__ __half   g_ohi [NOUT*NHID];         // w_out hi fp16           128 KB
__device__ __half   g_olo [NOUT*NHID];         // w_out lo fp16           128 KB
__device__ float    g_ch  [(size_t)MM*NHID];   // hidden synaptic input   67 MB
__device__ __half   g_sh  [(size_t)MM*NHID];   // hidden spikes fp16      33.5 MB
__device__ float    g_co  [MM*NOUT];           // output synaptic input   16.8 MB

// ================= PTX helpers =================
__device__ __forceinline__ uint32_t smem_u32(const void* p) {
    uint32_t a;
    asm("{ .reg .u64 t; cvta.to.shared.u64 t, %1; cvt.u32.u64 %0, t; }" : "=r"(a) : "l"(p));
    return a;
}
#define CP_ASYNC16(dst, src) \
    asm volatile("cp.async.cg.shared.global [%0], [%1], 16;" :: "r"(dst), "l"(src))
#define CP_COMMIT()  asm volatile("cp.async.commit_group;" ::: "memory")
#define CP_WAIT(n)   asm volatile("cp.async.wait_group %0;" :: "n"(n) : "memory")

#define LDSM_X4(r0,r1,r2,r3, a) \
    asm volatile("ldmatrix.sync.aligned.m8n8.x4.shared.b16 {%0,%1,%2,%3}, [%4];" \
        : "=r"(r0),"=r"(r1),"=r"(r2),"=r"(r3) : "r"(a))
#define MMA16816(d, a0,a1,a2,a3, b0,b1) \
    asm volatile("mma.sync.aligned.m16n8k16.row.col.f32.f16.f16.f32 " \
        "{%0,%1,%2,%3}, {%4,%5,%6,%7}, {%8,%9}, {%0,%1,%2,%3};" \
        : "+f"((d)[0]),"+f"((d)[1]),"+f"((d)[2]),"+f"((d)[3]) \
        : "r"(a0),"r"(a1),"r"(a2),"r"(a3),"r"(b0),"r"(b1))

#define SWZ(off) ((off) ^ (((off) >> 3) & 0x70))

// ================= conversion kernels =================
// spikes fp32 [MM][784] -> fp16 [MM][832] (pad zero); 4 cols/thread
__global__ void k_a16(const float* __restrict__ spikes) {
    int m = blockIdx.x;
    int c = threadIdx.x * 4;                 // 0..828
    __half2 h0, h1;
    if (c + 3 < NIN) {
        float4 v = *(const float4*)(spikes + (size_t)m*NIN + c);
        h0 = __floats2half2_rn(v.x, v.y);
        h1 = __floats2half2_rn(v.z, v.w);
    } else {
        float a0 = (c+0 < NIN) ? spikes[(size_t)m*NIN + c+0] : 0.f;
        float a1 = (c+1 < NIN) ? spikes[(size_t)m*NIN + c+1] : 0.f;
        float a2 = (c+2 < NIN) ? spikes[(size_t)m*NIN + c+2] : 0.f;
        float a3 = (c+3 < NIN) ? spikes[(size_t)m*NIN + c+3] : 0.f;
        h0 = __floats2half2_rn(a0, a1);
        h1 = __floats2half2_rn(a2, a3);
    }
    *(__half2*)(g_a16 + (size_t)m*KPAD + c)     = h0;
    *(__half2*)(g_a16 + (size_t)m*KPAD + c + 2) = h1;
}

// w_hidden [512][784] fp32 -> hi/lo fp16 [512][832]
__global__ void k_bsplit(const float* __restrict__ w) {
    int idx = blockIdx.x*blockDim.x + threadIdx.x;
    if (idx >= NHID*KPAD) return;
    int h = idx / KPAD, k = idx % KPAD;
    __half hi = __float2half_rn(0.f), lo = __float2half_rn(0.f);
    if (k < NIN) {
        float wv = w[h*NIN + k];
        hi = __float2half_rn(wv);
        lo = __float2half_rn(wv - __half2float(hi));
    }
    g_bhi[idx] = hi;
    g_blo[idx] = lo;
}

// w_out [128][512] fp32 -> hi/lo fp16 (already [n][k] layout for mma)
__global__ void k_osplit(const float* __restrict__ w) {
    int idx = blockIdx.x*blockDim.x + threadIdx.x;
    if (idx >= NOUT*NHID) return;
    float wv = w[idx];
    __half hi = __float2half_rn(wv);
    g_ohi[idx] = hi;
    g_olo[idx] = __float2half_rn(wv - __half2float(hi));
}

// ================= persistent GEMM core =================
// Warp tile 64x32, warps 2(m) x 4(n). Tiles assigned round-robin to CTAs;
// cp.async stream linearized across (tile, chunk): next tile's chunk 0 loads
// while current tile's last chunk computes + epilogue stores.
#define STAGE_BYTES 49152

template<int NCHUNKS, int AKSTRIDE, int NSTRIDE, int NTILE_N>
__device__ __forceinline__ void gemm_persist(
    const __half* a_g, const __half* bh_g, const __half* bl_g,
    float* c_g, int ntiles, char* smem)
{
    const int tid    = threadIdx.x;
    const int wid    = tid >> 5;
    const int lane   = tid & 31;
    const int warp_m = wid >> 2;            // 0..1  (64 rows)
    const int warp_n = wid &  3;            // 0..3  (32 cols)
    const int G      = gridDim.x;

    const uint32_t sbase = smem_u32(smem);

    auto load_chunk = [&](int t, int kc, int s) {
        const uint32_t st = sbase + s * STAGE_BYTES;
        const int m_base = (t / NTILE_N) * 128;
        const int n_base = (t % NTILE_N) * 128;
        const int kcol = kc * 64;
        #pragma unroll
        for (int it = 0; it < 4; it++) {
            int g = it * 256 + tid;
            int row = g >> 3, sub = g & 7;
            uint32_t off = row * 128 + sub * 16;
            const char* src = (const char*)(a_g + (size_t)(m_base + row)*AKSTRIDE + kcol) + sub*16;
            CP_ASYNC16(st + SWZ(off), src);
        }
        #pragma unroll
        for (int it = 0; it < 4; it++) {
            int g = it * 256 + tid;
            int row = g >> 3, sub = g & 7;
            uint32_t off = row * 128 + sub * 16;
            const char* srch = (const char*)(bh_g + (size_t)(n_base + row)*AKSTRIDE + kcol) + sub*16;
            const char* srcl = (const char*)(bl_g + (size_t)(n_base + row)*AKSTRIDE + kcol) + sub*16;
            CP_ASYNC16(st + 16384 + SWZ(off), srch);
            CP_ASYNC16(st + 32768 + SWZ(off), srcl);
        }
        CP_COMMIT();
    };

    float acc[4][4][4];
    #pragma unroll
    for (int i = 0; i < 4; i++)
        #pragma unroll
        for (int j = 0; j < 4; j++)
            #pragma unroll
            for (int q = 0; q < 4; q++) acc[i][j][q] = 0.f;

    int t_cur = blockIdx.x;                 // tile being computed
    if (t_cur >= ntiles) return;
    int t_ld = t_cur, c_ld = 0;             // next chunk to load
    load_chunk(t_ld, 0, 0);
    if (++c_ld == NCHUNKS) { c_ld = 0; t_ld += G; }

    const int lrow = lane & 15, lcol = (lane >> 4) * 16;
    const int erow = lane >> 2, ecol = (lane & 3) * 2;
    int c_cur = 0, buf = 0;

    #pragma unroll 1
    while (true) {
        CP_WAIT(0);
        __syncthreads();
        if (t_ld < ntiles) {
            load_chunk(t_ld, c_ld, buf ^ 1);
            if (++c_ld == NCHUNKS) { c_ld = 0; t_ld += G; }
        }

        const uint32_t sA  = sbase + buf * STAGE_BYTES;
        const uint32_t sBh = sA + 16384;
        const uint32_t sBl = sA + 32768;

        #pragma unroll
        for (int ks = 0; ks < 4; ks++) {
            uint32_t a[4][4], bh[2][4], bl[2][4];
            #pragma unroll
            for (int mt = 0; mt < 4; mt++) {
                uint32_t off = (uint32_t)(warp_m*64 + mt*16 + lrow)*128 + ks*32 + lcol;
                LDSM_X4(a[mt][0], a[mt][1], a[mt][2], a[mt][3], sA + SWZ(off));
            }
            #pragma unroll
            for (int nt = 0; nt < 2; nt++) {
                uint32_t off = (uint32_t)(warp_n*32 + nt*16 + lrow)*128 + ks*32 + lcol;
                uint32_t so = SWZ(off);
                LDSM_X4(bh[nt][0], bh[nt][1], bh[nt][2], bh[nt][3], sBh + so);
                LDSM_X4(bl[nt][0], bl[nt][1], bl[nt][2], bl[nt][3], sBl + so);
            }
            // hi pass (each acc touched once -> long RAW distance)
            #pragma unroll
            for (int mt = 0; mt < 4; mt++)
                #pragma unroll
                for (int nt = 0; nt < 2; nt++) {
                    MMA16816(acc[mt][nt*2+0], a[mt][0],a[mt][1],a[mt][2],a[mt][3],
                             bh[nt][0], bh[nt][2]);
                    MMA16816(acc[mt][nt*2+1], a[mt][0],a[mt][1],a[mt][2],a[mt][3],
                             bh[nt][1], bh[nt][3]);
                }
            // lo pass
            #pragma unroll
            for (int mt = 0; mt < 4; mt++)
                #pragma unroll
                for (int nt = 0; nt < 2; nt++) {
                    MMA16816(acc[mt][nt*2+0], a[mt][0],a[mt][1],a[mt][2],a[mt][3],
                             bl[nt][0], bl[nt][2]);
                    MMA16816(acc[mt][nt*2+1], a[mt][0],a[mt][1],a[mt][2],a[mt][3],
                             bl[nt][1], bl[nt][3]);
                }
        }

        buf ^= 1;
        if (c_cur == NCHUNKS - 1) {
            // epilogue for t_cur (register-only; overlaps next tile's load)
            const int m_base = (t_cur / NTILE_N) * 128;
            const int n_base = (t_cur % NTILE_N) * 128;
            #pragma unroll
            for (int mt = 0; mt < 4; mt++) {
                #pragma unroll
                for (int j = 0; j < 4; j++) {
                    int col = n_base + warp_n*32 + j*8 + ecol;
                    int r0  = m_base + warp_m*64 + mt*16 + erow;
                    float2 v0; v0.x = acc[mt][j][0]; v0.y = acc[mt][j][1];
                    float2 v1; v1.x = acc[mt][j][2]; v1.y = acc[mt][j][3];
                    *(float2*)(c_g + (size_t)r0*NSTRIDE + col)       = v0;
                    *(float2*)(c_g + (size_t)(r0 + 8)*NSTRIDE + col) = v1;
                    acc[mt][j][0] = 0.f; acc[mt][j][1] = 0.f;
                    acc[mt][j][2] = 0.f; acc[mt][j][3] = 0.f;
                }
            }
            c_cur = 0;
            t_cur += G;
            if (t_cur >= ntiles) break;
        } else {
            c_cur++;
        }
    }
}

__global__ void __launch_bounds__(256, 2) k_gemm1tc() {
    extern __shared__ char smem[];
    gemm_persist<NCH, KPAD, NHID, 4>(g_a16, g_bhi, g_blo, g_ch, MTILES*4, smem);
}

__global__ void __launch_bounds__(256, 2) k_gemm2tc() {
    extern __shared__ char smem[];
    gemm_persist<NCH2, NHID, NOUT, 1>(g_sh, g_ohi, g_olo, g_co, MTILES, smem);
}

// ================= LIF scan -> fp16 hidden spikes =================
__global__ void k_lif() {
    int gid = blockIdx.x*blockDim.x + threadIdx.x;   // b*512 + h
    float v = 0.0f, cur = 0.0f;
    float xs[8];
    #pragma unroll
    for (int p = 0; p < 8; p++) xs[p] = g_ch[(size_t)p*(BB*NHID) + gid];
    #pragma unroll 1
    for (int t0 = 0; t0 < TT; t0 += 8) {
        #pragma unroll
        for (int p = 0; p < 8; p++) {
            float x = xs[p];
            int tn = t0 + 8 + p;
            if (tn < TT) xs[p] = g_ch[(size_t)tn*(BB*NHID) + gid];
            v   = v + C_A*(cur - v);
            cur = cur*C_D + x;
            bool z = v > 1.0f;
            if (z) v = 0.0f;
            g_sh[(size_t)(t0 + p)*(BB*NHID) + gid] = __float2half_rn(z ? 1.0f : 0.0f);
        }
    }
}

// ================= LI scan with software prefetch =================
__global__ void k_li(float* __restrict__ out) {
    int gid = blockIdx.x*blockDim.x + threadIdx.x;
    float v = 0.0f, cur = 0.0f;
    float xs[8];
    #pragma unroll
    for (int p = 0; p < 8; p++) xs[p] = g_co[p*(BB*NOUT) + gid];
    #pragma unroll 1
    for (int t0 = 0; t0 < TT; t0 += 8) {
        #pragma unroll
        for (int p = 0; p < 8; p++) {
            float x = xs[p];
            int tn = t0 + 8 + p;
            if (tn < TT) xs[p] = g_co[tn*(BB*NOUT) + gid];
            v   = v + C_A*(cur - v);
            cur = cur*C_D + x;
            out[(t0 + p)*(BB*NOUT) + gid] = v;
        }
    }
}

// ================= launch =================
extern "C" void kernel_launch(void* const* d_in, const int* in_sizes, int n_in,
                              void* d_out, int out_size) {
    const float *spikes = nullptr, *wh = nullptr, *wo = nullptr;
    for (int i = 0; i < n_in; i++) {
        if      (in_sizes[i] == TT*BB*NIN) spikes = (const float*)d_in[i];
        else if (in_sizes[i] == NHID*NIN)  wh     = (const float*)d_in[i];
        else if (in_sizes[i] == NOUT*NHID) wo     = (const float*)d_in[i];
    }
    cudaFuncSetAttribute(k_gemm1tc, cudaFuncAttributeMaxDynamicSharedMemorySize,
                         2*STAGE_BYTES);
    cudaFuncSetAttribute(k_gemm2tc, cudaFuncAttributeMaxDynamicSharedMemorySize,
                         2*STAGE_BYTES);
    k_bsplit <<<(NHID*KPAD + 255)/256, 256>>>(wh);
    k_osplit <<<(NOUT*NHID + 255)/256, 256>>>(wo);
    k_a16    <<<MM, KPAD/4>>>(spikes);
    k_gemm1tc<<<G1GRID, 256, 2*STAGE_BYTES>>>();
    k_lif    <<<(BB*NHID)/256, 256>>>();
    k_gemm2tc<<<MTILES, 256, 2*STAGE_BYTES>>>();
    k_li     <<<(BB*NOUT)/256, 256>>>((float*)d_out);
}

// round 9
// speedup vs baseline: 1.0427x; 1.0427x over previous
#include <cuda_runtime.h>
#include <cuda_fp16.h>
#include <stdint.h>

// Problem constants
#define TT   256
#define BB   128
#define NIN  784
#define NHID 512
#define NOUT 128
#define MM   (TT*BB)        // 32768 (t,b) pairs
#define KPAD 832            // 784 padded to 13*64
#define NCH  13             // gemm1 K chunks of 64
#define NCH2 8              // gemm2 K chunks of 64 (512/64)
#define MTILES (MM/128)     // 256

// CUBA constants (exactly fp32-rounded like JAX)
#define C_A ((float)(1e-6*(1.0/6e-6)))           // 0.16666667f
#define C_D ((float)(1.0 - 1e-6*(1.0/6e-6)))     // 0.8333333f

// ---- scratch (device globals; no allocations allowed) ----
__device__ __half   g_a16 [(size_t)MM*KPAD];   // spikes fp16 K-padded    54.5 MB
__device__ __half   g_bhi [NHID*KPAD];         // w_hidden hi fp16        0.85 MB
__device__ __half   g_blo [NHID*KPAD];         // w_hidden lo fp16        0.85 MB
__device__ __half   g_ohi [NOUT*NHID];         // w_out hi fp16           128 KB
__device__ __half   g_olo [NOUT*NHID];         // w_out lo fp16           128 KB
__device__ float    g_ch  [(size_t)MM*NHID];   // hidden synaptic input   67 MB
__device__ __half   g_sh  [(size_t)MM*NHID];   // hidden spikes fp16      33.5 MB
__device__ float    g_co  [MM*NOUT];           // output synaptic input   16.8 MB

// ================= PTX helpers =================
__device__ __forceinline__ uint32_t smem_u32(const void* p) {
    uint32_t a;
    asm("{ .reg .u64 t; cvta.to.shared.u64 t, %1; cvt.u32.u64 %0, t; }" : "=r"(a) : "l"(p));
    return a;
}
#define CP_ASYNC16(dst, src) \
    asm volatile("cp.async.cg.shared.global [%0], [%1], 16;" :: "r"(dst), "l"(src))
#define CP_COMMIT()  asm volatile("cp.async.commit_group;" ::: "memory")
#define CP_WAIT(n)   asm volatile("cp.async.wait_group %0;" :: "n"(n) : "memory")

#define LDSM_X4(r0,r1,r2,r3, a) \
    asm volatile("ldmatrix.sync.aligned.m8n8.x4.shared.b16 {%0,%1,%2,%3}, [%4];" \
        : "=r"(r0),"=r"(r1),"=r"(r2),"=r"(r3) : "r"(a))
#define MMA16816(d, a0,a1,a2,a3, b0,b1) \
    asm volatile("mma.sync.aligned.m16n8k16.row.col.f32.f16.f16.f32 " \
        "{%0,%1,%2,%3}, {%4,%5,%6,%7}, {%8,%9}, {%0,%1,%2,%3};" \
        : "+f"((d)[0]),"+f"((d)[1]),"+f"((d)[2]),"+f"((d)[3]) \
        : "r"(a0),"r"(a1),"r"(a2),"r"(a3),"r"(b0),"r"(b1))

#define SWZ(off) ((off) ^ (((off) >> 3) & 0x70))

// ================= conversion kernels =================
// spikes fp32 [MM][784] -> fp16 [MM][832] (pad zero); 4 cols/thread (R7 version)
__global__ void k_a16(const float* __restrict__ spikes) {
    int m = blockIdx.x;
    int c = threadIdx.x * 4;                 // 0..828
    __half2 h0, h1;
    if (c + 3 < NIN) {
        float4 v = *(const float4*)(spikes + (size_t)m*NIN + c);
        h0 = __floats2half2_rn(v.x, v.y);
        h1 = __floats2half2_rn(v.z, v.w);
    } else {
        float a0 = (c+0 < NIN) ? spikes[(size_t)m*NIN + c+0] : 0.f;
        float a1 = (c+1 < NIN) ? spikes[(size_t)m*NIN + c+1] : 0.f;
        float a2 = (c+2 < NIN) ? spikes[(size_t)m*NIN + c+2] : 0.f;
        float a3 = (c+3 < NIN) ? spikes[(size_t)m*NIN + c+3] : 0.f;
        h0 = __floats2half2_rn(a0, a1);
        h1 = __floats2half2_rn(a2, a3);
    }
    *(__half2*)(g_a16 + (size_t)m*KPAD + c)     = h0;
    *(__half2*)(g_a16 + (size_t)m*KPAD + c + 2) = h1;
}

// w_hidden [512][784] fp32 -> hi/lo fp16 [512][832]
__global__ void k_bsplit(const float* __restrict__ w) {
    int idx = blockIdx.x*blockDim.x + threadIdx.x;
    if (idx >= NHID*KPAD) return;
    int h = idx / KPAD, k = idx % KPAD;
    __half hi = __float2half_rn(0.f), lo = __float2half_rn(0.f);
    if (k < NIN) {
        float wv = w[h*NIN + k];
        hi = __float2half_rn(wv);
        lo = __float2half_rn(wv - __half2float(hi));
    }
    g_bhi[idx] = hi;
    g_blo[idx] = lo;
}

// w_out [128][512] fp32 -> hi/lo fp16 (already [n][k] layout for mma)
__global__ void k_osplit(const float* __restrict__ w) {
    int idx = blockIdx.x*blockDim.x + threadIdx.x;
    if (idx >= NOUT*NHID) return;
    float wv = w[idx];
    __half hi = __float2half_rn(wv);
    g_ohi[idx] = hi;
    g_olo[idx] = __float2half_rn(wv - __half2float(hi));
}

// ================= GEMM1 (exact R6 core): warp tile 32x64, warps 4(m) x 2(n) =================
#define STAGE_BYTES 49152

__global__ void __launch_bounds__(256, 2) k_gemm1tc() {
    extern __shared__ char smem[];
    const int tid    = threadIdx.x;
    const int wid    = tid >> 5;
    const int lane   = tid & 31;
    const int warp_m = wid >> 1;
    const int warp_n = wid &  1;
    const int m_base = blockIdx.x * 128;
    const int n_base = blockIdx.y * 128;

    const uint32_t sbase = smem_u32(smem);

    auto load_tile = [&](int kc, int s) {
        const uint32_t st = sbase + s * STAGE_BYTES;
        const int kcol = kc * 64;
        #pragma unroll
        for (int it = 0; it < 4; it++) {
            int g = it * 256 + tid;
            int row = g >> 3, sub = g & 7;
            uint32_t off = row * 128 + sub * 16;
            const char* src = (const char*)(g_a16 + (size_t)(m_base + row)*KPAD + kcol) + sub*16;
            CP_ASYNC16(st + SWZ(off), src);
        }
        #pragma unroll
        for (int it = 0; it < 4; it++) {
            int g = it * 256 + tid;
            int row = g >> 3, sub = g & 7;
            uint32_t off = row * 128 + sub * 16;
            const char* srch = (const char*)(g_bhi + (size_t)(n_base + row)*KPAD + kcol) + sub*16;
            const char* srcl = (const char*)(g_blo + (size_t)(n_base + row)*KPAD + kcol) + sub*16;
            CP_ASYNC16(st + 16384 + SWZ(off), srch);
            CP_ASYNC16(st + 32768 + SWZ(off), srcl);
        }
        CP_COMMIT();
    };

    float acc[2][8][4];
    #pragma unroll
    for (int i = 0; i < 2; i++)
        #pragma unroll
        for (int j = 0; j < 8; j++)
            #pragma unroll
            for (int q = 0; q < 4; q++) acc[i][j][q] = 0.f;

    load_tile(0, 0);

    const int lrow = lane & 15, lcol = (lane >> 4) * 16;

    #pragma unroll 1
    for (int c = 0; c < NCH; c++) {
        const int buf = c & 1;
        if (c + 1 < NCH) { load_tile(c + 1, buf ^ 1); CP_WAIT(1); }
        else            { CP_WAIT(0); }
        __syncthreads();

        const uint32_t sA = sbase + buf * STAGE_BYTES;
        const uint32_t sBh = sA + 16384;
        const uint32_t sBl = sA + 32768;

        #pragma unroll
        for (int ks = 0; ks < 4; ks++) {
            uint32_t a[2][4], bh[4][4], bl[4][4];
            #pragma unroll
            for (int mt = 0; mt < 2; mt++) {
                uint32_t off = (uint32_t)(warp_m*32 + mt*16 + lrow)*128 + ks*32 + lcol;
                LDSM_X4(a[mt][0], a[mt][1], a[mt][2], a[mt][3], sA + SWZ(off));
            }
            #pragma unroll
            for (int nt = 0; nt < 4; nt++) {
                uint32_t off = (uint32_t)(warp_n*64 + nt*16 + lrow)*128 + ks*32 + lcol;
                uint32_t so = SWZ(off);
                LDSM_X4(bh[nt][0], bh[nt][1], bh[nt][2], bh[nt][3], sBh + so);
                LDSM_X4(bl[nt][0], bl[nt][1], bl[nt][2], bl[nt][3], sBl + so);
            }
            #pragma unroll
            for (int mt = 0; mt < 2; mt++)
                #pragma unroll
                for (int nt = 0; nt < 4; nt++) {
                    MMA16816(acc[mt][nt*2+0], a[mt][0],a[mt][1],a[mt][2],a[mt][3],
                             bh[nt][0], bh[nt][2]);
                    MMA16816(acc[mt][nt*2+1], a[mt][0],a[mt][1],a[mt][2],a[mt][3],
                             bh[nt][1], bh[nt][3]);
                    MMA16816(acc[mt][nt*2+0], a[mt][0],a[mt][1],a[mt][2],a[mt][3],
                             bl[nt][0], bl[nt][2]);
                    MMA16816(acc[mt][nt*2+1], a[mt][0],a[mt][1],a[mt][2],a[mt][3],
                             bl[nt][1], bl[nt][3]);
                }
        }
        __syncthreads();
    }

    const int erow = lane >> 2, ecol = (lane & 3) * 2;
    #pragma unroll
    for (int mt = 0; mt < 2; mt++) {
        #pragma unroll
        for (int nt = 0; nt < 8; nt++) {
            int col = n_base + warp_n*64 + nt*8 + ecol;
            int r0  = m_base + warp_m*32 + mt*16 + erow;
            float2 v0; v0.x = acc[mt][nt][0]; v0.y = acc[mt][nt][1];
            float2 v1; v1.x = acc[mt][nt][2]; v1.y = acc[mt][nt][3];
            *(float2*)(g_ch + (size_t)r0*NHID + col)       = v0;
            *(float2*)(g_ch + (size_t)(r0 + 8)*NHID + col) = v1;
        }
    }
}

// ================= GEMM2 (exact R6 core): K=512, N=128 =================
__global__ void __launch_bounds__(256, 2) k_gemm2tc() {
    extern __shared__ char smem[];
    const int tid    = threadIdx.x;
    const int wid    = tid >> 5;
    const int lane   = tid & 31;
    const int warp_m = wid >> 1;
    const int warp_n = wid &  1;
    const int m_base = blockIdx.x * 128;

    const uint32_t sbase = smem_u32(smem);

    auto load_tile = [&](int kc, int s) {
        const uint32_t st = sbase + s * STAGE_BYTES;
        const int kcol = kc * 64;
        #pragma unroll
        for (int it = 0; it < 4; it++) {
            int g = it * 256 + tid;
            int row = g >> 3, sub = g & 7;
            uint32_t off = row * 128 + sub * 16;
            const char* src = (const char*)(g_sh + (size_t)(m_base + row)*NHID + kcol) + sub*16;
            CP_ASYNC16(st + SWZ(off), src);
        }
        #pragma unroll
        for (int it = 0; it < 4; it++) {
            int g = it * 256 + tid;
            int row = g >> 3, sub = g & 7;
            uint32_t off = row * 128 + sub * 16;
            const char* srch = (const char*)(g_ohi + (size_t)row*NHID + kcol) + sub*16;
            const char* srcl = (const char*)(g_olo + (size_t)row*NHID + kcol) + sub*16;
            CP_ASYNC16(st + 16384 + SWZ(off), srch);
            CP_ASYNC16(st + 32768 + SWZ(off), srcl);
        }
        CP_COMMIT();
    };

    float acc[2][8][4];
    #pragma unroll
    for (int i = 0; i < 2; i++)
        #pragma unroll
        for (int j = 0; j < 8; j++)
            #pragma unroll
            for (int q = 0; q < 4; q++) acc[i][j][q] = 0.f;

    load_tile(0, 0);

    const int lrow = lane & 15, lcol = (lane >> 4) * 16;

    #pragma unroll 1
    for (int c = 0; c < NCH2; c++) {
        const int buf = c & 1;
        if (c + 1 < NCH2) { load_tile(c + 1, buf ^ 1); CP_WAIT(1); }
        else             { CP_WAIT(0); }
        __syncthreads();

        const uint32_t sA = sbase + buf * STAGE_BYTES;
        const uint32_t sBh = sA + 16384;
        const uint32_t sBl = sA + 32768;

        #pragma unroll
        for (int ks = 0; ks < 4; ks++) {
            uint32_t a[2][4], bh[4][4], bl[4][4];
            #pragma unroll
            for (int mt = 0; mt < 2; mt++) {
                uint32_t off = (uint32_t)(warp_m*32 + mt*16 + lrow)*128 + ks*32 + lcol;
                LDSM_X4(a[mt][0], a[mt][1], a[mt][2], a[mt][3], sA + SWZ(off));
            }
            #pragma unroll
            for (int nt = 0; nt < 4; nt++) {
                uint32_t off = (uint32_t)(warp_n*64 + nt*16 + lrow)*128 + ks*32 + lcol;
                uint32_t so = SWZ(off);
                LDSM_X4(bh[nt][0], bh[nt][1], bh[nt][2], bh[nt][3], sBh + so);
                LDSM_X4(bl[nt][0], bl[nt][1], bl[nt][2], bl[nt][3], sBl + so);
            }
            #pragma unroll
            for (int mt = 0; mt < 2; mt++)
                #pragma unroll
                for (int nt = 0; nt < 4; nt++) {
                    MMA16816(acc[mt][nt*2+0], a[mt][0],a[mt][1],a[mt][2],a[mt][3],
                             bh[nt][0], bh[nt][2]);
                    MMA16816(acc[mt][nt*2+1], a[mt][0],a[mt][1],a[mt][2],a[mt][3],
                             bh[nt][1], bh[nt][3]);
                    MMA16816(acc[mt][nt*2+0], a[mt][0],a[mt][1],a[mt][2],a[mt][3],
                             bl[nt][0], bl[nt][2]);
                    MMA16816(acc[mt][nt*2+1], a[mt][0],a[mt][1],a[mt][2],a[mt][3],
                             bl[nt][1], bl[nt][3]);
                }
        }
        __syncthreads();
    }

    const int erow = lane >> 2, ecol = (lane & 3) * 2;
    #pragma unroll
    for (int mt = 0; mt < 2; mt++) {
        #pragma unroll
        for (int nt = 0; nt < 8; nt++) {
            int col = warp_n*64 + nt*8 + ecol;
            int r0  = m_base + warp_m*32 + mt*16 + erow;
            float2 v0; v0.x = acc[mt][nt][0]; v0.y = acc[mt][nt][1];
            float2 v1; v1.x = acc[mt][nt][2]; v1.y = acc[mt][nt][3];
            *(float2*)(g_co + (size_t)r0*NOUT + col)       = v0;
            *(float2*)(g_co + (size_t)(r0 + 8)*NOUT + col) = v1;
        }
    }
}

// ================= LIF scan -> fp16 hidden spikes =================
__global__ void k_lif() {
    int gid = blockIdx.x*blockDim.x + threadIdx.x;   // b*512 + h
    float v = 0.0f, cur = 0.0f;
    float xs[8];
    #pragma unroll
    for (int p = 0; p < 8; p++) xs[p] = g_ch[(size_t)p*(BB*NHID) + gid];
    #pragma unroll 1
    for (int t0 = 0; t0 < TT; t0 += 8) {
        #pragma unroll
        for (int p = 0; p < 8; p++) {
            float x = xs[p];
            int tn = t0 + 8 + p;
            if (tn < TT) xs[p] = g_ch[(size_t)tn*(BB*NHID) + gid];
            v   = v + C_A*(cur - v);
            cur = cur*C_D + x;
            bool z = v > 1.0f;
            if (z) v = 0.0f;
            g_sh[(size_t)(t0 + p)*(BB*NHID) + gid] = __float2half_rn(z ? 1.0f : 0.0f);
        }
    }
}

// ================= LI scan with software prefetch =================
__global__ void k_li(float* __restrict__ out) {
    int gid = blockIdx.x*blockDim.x + threadIdx.x;
    float v = 0.0f, cur = 0.0f;
    float xs[8];
    #pragma unroll
    for (int p = 0; p < 8; p++) xs[p] = g_co[p*(BB*NOUT) + gid];
    #pragma unroll 1
    for (int t0 = 0; t0 < TT; t0 += 8) {
        #pragma unroll
        for (int p = 0; p < 8; p++) {
            float x = xs[p];
            int tn = t0 + 8 + p;
            if (tn < TT) xs[p] = g_co[tn*(BB*NOUT) + gid];
            v   = v + C_A*(cur - v);
            cur = cur*C_D + x;
            out[(t0 + p)*(BB*NOUT) + gid] = v;
        }
    }
}

// ================= launch =================
extern "C" void kernel_launch(void* const* d_in, const int* in_sizes, int n_in,
                              void* d_out, int out_size) {
    const float *spikes = nullptr, *wh = nullptr, *wo = nullptr;
    for (int i = 0; i < n_in; i++) {
        if      (in_sizes[i] == TT*BB*NIN) spikes = (const float*)d_in[i];
        else if (in_sizes[i] == NHID*NIN)  wh     = (const float*)d_in[i];
        else if (in_sizes[i] == NOUT*NHID) wo     = (const float*)d_in[i];
    }
    cudaFuncSetAttribute(k_gemm1tc, cudaFuncAttributeMaxDynamicSharedMemorySize,
                         2*STAGE_BYTES);
    cudaFuncSetAttribute(k_gemm2tc, cudaFuncAttributeMaxDynamicSharedMemorySize,
                         2*STAGE_BYTES);
    k_bsplit <<<(NHID*KPAD + 255)/256, 256>>>(wh);
    k_osplit <<<(NOUT*NHID + 255)/256, 256>>>(wo);
    k_a16    <<<MM, KPAD/4>>>(spikes);
    k_gemm1tc<<<dim3(MTILES, NHID/128), 256, 2*STAGE_BYTES>>>();
    k_lif    <<<(BB*NHID)/256, 256>>>();
    k_gemm2tc<<<MTILES, 256, 2*STAGE_BYTES>>>();
    k_li     <<<(BB*NOUT)/256, 256>>>((float*)d_out);
}

// round 10
// speedup vs baseline: 1.1353x; 1.0888x over previous
#include <cuda_runtime.h>
#include <cuda_fp16.h>
#include <stdint.h>

// Problem constants
#define TT   256
#define BB   128
#define NIN  784
#define NHID 512
#define NOUT 128
#define MM   (TT*BB)        // 32768 (t,b) pairs
#define KPAD 832            // 784 padded to 13*64
#define NCH  13             // gemm1 K chunks of 64
#define NCH2 8              // gemm2 K chunks of 64 (512/64)
#define MTILES (MM/128)     // 256

// CUBA constants (exactly fp32-rounded like JAX)
#define C_A ((float)(1e-6*(1.0/6e-6)))           // 0.16666667f
#define C_D ((float)(1.0 - 1e-6*(1.0/6e-6)))     // 0.8333333f

// ---- scratch (device globals; no allocations allowed) ----
__device__ __half   g_a16 [(size_t)MM*KPAD];   // spikes fp16 K-padded    54.5 MB
__device__ __half   g_bhi [NHID*KPAD];         // w_hidden hi fp16        0.85 MB
__device__ __half   g_blo [NHID*KPAD];         // w_hidden lo fp16        0.85 MB
__device__ __half   g_ohi [NOUT*NHID];         // w_out hi fp16           128 KB
__device__ __half   g_olo [NOUT*NHID];         // w_out lo fp16           128 KB
__device__ float    g_ch  [(size_t)MM*NHID];   // hidden synaptic input   67 MB
__device__ __half   g_sh  [(size_t)MM*NHID];   // hidden spikes fp16      33.5 MB
__device__ float    g_co  [MM*NOUT];           // output synaptic input   16.8 MB

// ================= PTX helpers =================
__device__ __forceinline__ uint32_t smem_u32(const void* p) {
    uint32_t a;
    asm("{ .reg .u64 t; cvta.to.shared.u64 t, %1; cvt.u32.u64 %0, t; }" : "=r"(a) : "l"(p));
    return a;
}
#define CP_ASYNC16(dst, src) \
    asm volatile("cp.async.cg.shared.global [%0], [%1], 16;" :: "r"(dst), "l"(src))
#define CP_COMMIT()  asm volatile("cp.async.commit_group;" ::: "memory")
#define CP_WAIT(n)   asm volatile("cp.async.wait_group %0;" :: "n"(n) : "memory")

#define LDSM_X4(r0,r1,r2,r3, a) \
    asm volatile("ldmatrix.sync.aligned.m8n8.x4.shared.b16 {%0,%1,%2,%3}, [%4];" \
        : "=r"(r0),"=r"(r1),"=r"(r2),"=r"(r3) : "r"(a))
#define MMA16816(d, a0,a1,a2,a3, b0,b1) \
    asm volatile("mma.sync.aligned.m16n8k16.row.col.f32.f16.f16.f32 " \
        "{%0,%1,%2,%3}, {%4,%5,%6,%7}, {%8,%9}, {%0,%1,%2,%3};" \
        : "+f"((d)[0]),"+f"((d)[1]),"+f"((d)[2]),"+f"((d)[3]) \
        : "r"(a0),"r"(a1),"r"(a2),"r"(a3),"r"(b0),"r"(b1))

#define SWZ(off) ((off) ^ (((off) >> 3) & 0x70))

// ================= conversion kernels =================
// spikes fp32 [MM][784] -> fp16 [MM][832]. One thread per 16B output group.
// 832/8 = 104 groups per row; NIN/8 = 98 exactly, so groups 98..103 are pure zero.
#define AGRP 104
__global__ void k_a16(const float* __restrict__ spikes) {
    int idx = blockIdx.x*blockDim.x + threadIdx.x;
    if (idx >= MM*AGRP) return;
    int m = idx / AGRP, grp = idx - m*AGRP;
    uint4 out;
    if (grp < 98) {
        const float4* src = (const float4*)(spikes + (size_t)m*NIN + grp*8);
        float4 v0 = src[0];
        float4 v1 = src[1];
        __half2 h0 = __floats2half2_rn(v0.x, v0.y);
        __half2 h1 = __floats2half2_rn(v0.z, v0.w);
        __half2 h2 = __floats2half2_rn(v1.x, v1.y);
        __half2 h3 = __floats2half2_rn(v1.z, v1.w);
        out.x = *(uint32_t*)&h0; out.y = *(uint32_t*)&h1;
        out.z = *(uint32_t*)&h2; out.w = *(uint32_t*)&h3;
    } else {
        out.x = out.y = out.z = out.w = 0u;
    }
    *(uint4*)(g_a16 + (size_t)m*KPAD + grp*8) = out;
}

// combined weight split: w_hidden -> g_bhi/g_blo, w_out -> g_ohi/g_olo
__global__ void k_wsplit(const float* __restrict__ wh, const float* __restrict__ wo) {
    int idx = blockIdx.x*blockDim.x + threadIdx.x;
    if (idx < NHID*KPAD) {
        int h = idx / KPAD, k = idx - h*KPAD;
        __half hi = __float2half_rn(0.f), lo = __float2half_rn(0.f);
        if (k < NIN) {
            float wv = wh[h*NIN + k];
            hi = __float2half_rn(wv);
            lo = __float2half_rn(wv - __half2float(hi));
        }
        g_bhi[idx] = hi;
        g_blo[idx] = lo;
    } else {
        int j = idx - NHID*KPAD;
        if (j < NOUT*NHID) {
            float wv = wo[j];
            __half hi = __float2half_rn(wv);
            g_ohi[j] = hi;
            g_olo[j] = __float2half_rn(wv - __half2float(hi));
        }
    }
}

// ================= GEMM1 (frozen R6 core): warp tile 32x64, warps 4(m) x 2(n) =================
#define STAGE_BYTES 49152

__global__ void __launch_bounds__(256, 2) k_gemm1tc() {
    extern __shared__ char smem[];
    const int tid    = threadIdx.x;
    const int wid    = tid >> 5;
    const int lane   = tid & 31;
    const int warp_m = wid >> 1;
    const int warp_n = wid &  1;
    const int m_base = blockIdx.x * 128;
    const int n_base = blockIdx.y * 128;

    const uint32_t sbase = smem_u32(smem);

    auto load_tile = [&](int kc, int s) {
        const uint32_t st = sbase + s * STAGE_BYTES;
        const int kcol = kc * 64;
        #pragma unroll
        for (int it = 0; it < 4; it++) {
            int g = it * 256 + tid;
            int row = g >> 3, sub = g & 7;
            uint32_t off = row * 128 + sub * 16;
            const char* src = (const char*)(g_a16 + (size_t)(m_base + row)*KPAD + kcol) + sub*16;
            CP_ASYNC16(st + SWZ(off), src);
        }
        #pragma unroll
        for (int it = 0; it < 4; it++) {
            int g = it * 256 + tid;
            int row = g >> 3, sub = g & 7;
            uint32_t off = row * 128 + sub * 16;
            const char* srch = (const char*)(g_bhi + (size_t)(n_base + row)*KPAD + kcol) + sub*16;
            const char* srcl = (const char*)(g_blo + (size_t)(n_base + row)*KPAD + kcol) + sub*16;
            CP_ASYNC16(st + 16384 + SWZ(off), srch);
            CP_ASYNC16(st + 32768 + SWZ(off), srcl);
        }
        CP_COMMIT();
    };

    float acc[2][8][4];
    #pragma unroll
    for (int i = 0; i < 2; i++)
        #pragma unroll
        for (int j = 0; j < 8; j++)
            #pragma unroll
            for (int q = 0; q < 4; q++) acc[i][j][q] = 0.f;

    load_tile(0, 0);

    const int lrow = lane & 15, lcol = (lane >> 4) * 16;

    #pragma unroll 1
    for (int c = 0; c < NCH; c++) {
        const int buf = c & 1;
        if (c + 1 < NCH) { load_tile(c + 1, buf ^ 1); CP_WAIT(1); }
        else            { CP_WAIT(0); }
        __syncthreads();

        const uint32_t sA = sbase + buf * STAGE_BYTES;
        const uint32_t sBh = sA + 16384;
        const uint32_t sBl = sA + 32768;

        #pragma unroll
        for (int ks = 0; ks < 4; ks++) {
            uint32_t a[2][4], bh[4][4], bl[4][4];
            #pragma unroll
            for (int mt = 0; mt < 2; mt++) {
                uint32_t off = (uint32_t)(warp_m*32 + mt*16 + lrow)*128 + ks*32 + lcol;
                LDSM_X4(a[mt][0], a[mt][1], a[mt][2], a[mt][3], sA + SWZ(off));
            }
            #pragma unroll
            for (int nt = 0; nt < 4; nt++) {
                uint32_t off = (uint32_t)(warp_n*64 + nt*16 + lrow)*128 + ks*32 + lcol;
                uint32_t so = SWZ(off);
                LDSM_X4(bh[nt][0], bh[nt][1], bh[nt][2], bh[nt][3], sBh + so);
                LDSM_X4(bl[nt][0], bl[nt][1], bl[nt][2], bl[nt][3], sBl + so);
            }
            #pragma unroll
            for (int mt = 0; mt < 2; mt++)
                #pragma unroll
                for (int nt = 0; nt < 4; nt++) {
                    MMA16816(acc[mt][nt*2+0], a[mt][0],a[mt][1],a[mt][2],a[mt][3],
                             bh[nt][0], bh[nt][2]);
                    MMA16816(acc[mt][nt*2+1], a[mt][0],a[mt][1],a[mt][2],a[mt][3],
                             bh[nt][1], bh[nt][3]);
                    MMA16816(acc[mt][nt*2+0], a[mt][0],a[mt][1],a[mt][2],a[mt][3],
                             bl[nt][0], bl[nt][2]);
                    MMA16816(acc[mt][nt*2+1], a[mt][0],a[mt][1],a[mt][2],a[mt][3],
                             bl[nt][1], bl[nt][3]);
                }
        }
        __syncthreads();
    }

    const int erow = lane >> 2, ecol = (lane & 3) * 2;
    #pragma unroll
    for (int mt = 0; mt < 2; mt++) {
        #pragma unroll
        for (int nt = 0; nt < 8; nt++) {
            int col = n_base + warp_n*64 + nt*8 + ecol;
            int r0  = m_base + warp_m*32 + mt*16 + erow;
            float2 v0; v0.x = acc[mt][nt][0]; v0.y = acc[mt][nt][1];
            float2 v1; v1.x = acc[mt][nt][2]; v1.y = acc[mt][nt][3];
            *(float2*)(g_ch + (size_t)r0*NHID + col)       = v0;
            *(float2*)(g_ch + (size_t)(r0 + 8)*NHID + col) = v1;
        }
    }
}

// ================= GEMM2 (frozen R6 core): K=512, N=128 =================
__global__ void __launch_bounds__(256, 2) k_gemm2tc() {
    extern __shared__ char smem[];
    const int tid    = threadIdx.x;
    const int wid    = tid >> 5;
    const int lane   = tid & 31;
    const int warp_m = wid >> 1;
    const int warp_n = wid &  1;
    const int m_base = blockIdx.x * 128;

    const uint32_t sbase = smem_u32(smem);

    auto load_tile = [&](int kc, int s) {
        const uint32_t st = sbase + s * STAGE_BYTES;
        const int kcol = kc * 64;
        #pragma unroll
        for (int it = 0; it < 4; it++) {
            int g = it * 256 + tid;
            int row = g >> 3, sub = g & 7;
            uint32_t off = row * 128 + sub * 16;
            const char* src = (const char*)(g_sh + (size_t)(m_base + row)*NHID + kcol) + sub*16;
            CP_ASYNC16(st + SWZ(off), src);
        }
        #pragma unroll
        for (int it = 0; it < 4; it++) {
            int g = it * 256 + tid;
            int row = g >> 3, sub = g & 7;
            uint32_t off = row * 128 + sub * 16;
            const char* srch = (const char*)(g_ohi + (size_t)row*NHID + kcol) + sub*16;
            const char* srcl = (const char*)(g_olo + (size_t)row*NHID + kcol) + sub*16;
            CP_ASYNC16(st + 16384 + SWZ(off), srch);
            CP_ASYNC16(st + 32768 + SWZ(off), srcl);
        }
        CP_COMMIT();
    };

    float acc[2][8][4];
    #pragma unroll
    for (int i = 0; i < 2; i++)
        #pragma unroll
        for (int j = 0; j < 8; j++)
            #pragma unroll
            for (int q = 0; q < 4; q++) acc[i][j][q] = 0.f;

    load_tile(0, 0);

    const int lrow = lane & 15, lcol = (lane >> 4) * 16;

    #pragma unroll 1
    for (int c = 0; c < NCH2; c++) {
        const int buf = c & 1;
        if (c + 1 < NCH2) { load_tile(c + 1, buf ^ 1); CP_WAIT(1); }
        else             { CP_WAIT(0); }
        __syncthreads();

        const uint32_t sA = sbase + buf * STAGE_BYTES;
        const uint32_t sBh = sA + 16384;
        const uint32_t sBl = sA + 32768;

        #pragma unroll
        for (int ks = 0; ks < 4; ks++) {
            uint32_t a[2][4], bh[4][4], bl[4][4];
            #pragma unroll
            for (int mt = 0; mt < 2; mt++) {
                uint32_t off = (uint32_t)(warp_m*32 + mt*16 + lrow)*128 + ks*32 + lcol;
                LDSM_X4(a[mt][0], a[mt][1], a[mt][2], a[mt][3], sA + SWZ(off));
            }
            #pragma unroll
            for (int nt = 0; nt < 4; nt++) {
                uint32_t off = (uint32_t)(warp_n*64 + nt*16 + lrow)*128 + ks*32 + lcol;
                uint32_t so = SWZ(off);
                LDSM_X4(bh[nt][0], bh[nt][1], bh[nt][2], bh[nt][3], sBh + so);
                LDSM_X4(bl[nt][0], bl[nt][1], bl[nt][2], bl[nt][3], sBl + so);
            }
            #pragma unroll
            for (int mt = 0; mt < 2; mt++)
                #pragma unroll
                for (int nt = 0; nt < 4; nt++) {
                    MMA16816(acc[mt][nt*2+0], a[mt][0],a[mt][1],a[mt][2],a[mt][3],
                             bh[nt][0], bh[nt][2]);
                    MMA16816(acc[mt][nt*2+1], a[mt][0],a[mt][1],a[mt][2],a[mt][3],
                             bh[nt][1], bh[nt][3]);
                    MMA16816(acc[mt][nt*2+0], a[mt][0],a[mt][1],a[mt][2],a[mt][3],
                             bl[nt][0], bl[nt][2]);
                    MMA16816(acc[mt][nt*2+1], a[mt][0],a[mt][1],a[mt][2],a[mt][3],
                             bl[nt][1], bl[nt][3]);
                }
        }
        __syncthreads();
    }

    const int erow = lane >> 2, ecol = (lane & 3) * 2;
    #pragma unroll
    for (int mt = 0; mt < 2; mt++) {
        #pragma unroll
        for (int nt = 0; nt < 8; nt++) {
            int col = warp_n*64 + nt*8 + ecol;
            int r0  = m_base + warp_m*32 + mt*16 + erow;
            float2 v0; v0.x = acc[mt][nt][0]; v0.y = acc[mt][nt][1];
            float2 v1; v1.x = acc[mt][nt][2]; v1.y = acc[mt][nt][3];
            *(float2*)(g_co + (size_t)r0*NOUT + col)       = v0;
            *(float2*)(g_co + (size_t)(r0 + 8)*NOUT + col) = v1;
        }
    }
}

// ================= LIF scan -> fp16 hidden spikes (prefetch 16, streaming loads) =================
__global__ void k_lif() {
    int gid = blockIdx.x*blockDim.x + threadIdx.x;   // b*512 + h
    float v = 0.0f, cur = 0.0f;
    float xs[16];
    #pragma unroll
    for (int p = 0; p < 16; p++) xs[p] = __ldcs(g_ch + (size_t)p*(BB*NHID) + gid);
    #pragma unroll 1
    for (int t0 = 0; t0 < TT; t0 += 16) {
        #pragma unroll
        for (int p = 0; p < 16; p++) {
            float x = xs[p];
            int tn = t0 + 16 + p;
            if (tn < TT) xs[p] = __ldcs(g_ch + (size_t)tn*(BB*NHID) + gid);
            v   = v + C_A*(cur - v);
            cur = cur*C_D + x;
            bool z = v > 1.0f;
            if (z) v = 0.0f;
            g_sh[(size_t)(t0 + p)*(BB*NHID) + gid] = __float2half_rn(z ? 1.0f : 0.0f);
        }
    }
}

// ================= LI scan (prefetch 32, streaming loads) =================
__global__ void k_li(float* __restrict__ out) {
    int gid = blockIdx.x*blockDim.x + threadIdx.x;   // b*128 + o
    float v = 0.0f, cur = 0.0f;
    float xs[32];
    #pragma unroll
    for (int p = 0; p < 32; p++) xs[p] = __ldcs(g_co + p*(BB*NOUT) + gid);
    #pragma unroll 1
    for (int t0 = 0; t0 < TT; t0 += 32) {
        #pragma unroll
        for (int p = 0; p < 32; p++) {
            float x = xs[p];
            int tn = t0 + 32 + p;
            if (tn < TT) xs[p] = __ldcs(g_co + tn*(BB*NOUT) + gid);
            v   = v + C_A*(cur - v);
            cur = cur*C_D + x;
            out[(t0 + p)*(BB*NOUT) + gid] = v;
        }
    }
}

// ================= launch =================
extern "C" void kernel_launch(void* const* d_in, const int* in_sizes, int n_in,
                              void* d_out, int out_size) {
    const float *spikes = nullptr, *wh = nullptr, *wo = nullptr;
    for (int i = 0; i < n_in; i++) {
        if      (in_sizes[i] == TT*BB*NIN) spikes = (const float*)d_in[i];
        else if (in_sizes[i] == NHID*NIN)  wh     = (const float*)d_in[i];
        else if (in_sizes[i] == NOUT*NHID) wo     = (const float*)d_in[i];
    }
    cudaFuncSetAttribute(k_gemm1tc, cudaFuncAttributeMaxDynamicSharedMemorySize,
                         2*STAGE_BYTES);
    cudaFuncSetAttribute(k_gemm2tc, cudaFuncAttributeMaxDynamicSharedMemorySize,
                         2*STAGE_BYTES);
    k_wsplit <<<(NHID*KPAD + NOUT*NHID + 255)/256, 256>>>(wh, wo);
    k_a16    <<<(MM*AGRP + 255)/256, 256>>>(spikes);
    k_gemm1tc<<<dim3(MTILES, NHID/128), 256, 2*STAGE_BYTES>>>();
    k_lif    <<<(BB*NHID)/256, 256>>>();
    k_gemm2tc<<<MTILES, 256, 2*STAGE_BYTES>>>();
    k_li     <<<(BB*NOUT)/256, 256>>>((float*)d_out);
}

// round 11
// speedup vs baseline: 1.1356x; 1.0003x over previous
#include <cuda_runtime.h>
#include <cuda_fp16.h>
#include <stdint.h>

// Problem constants
#define TT   256
#define BB   128
#define NIN  784
#define NHID 512
#define NOUT 128
#define MM   (TT*BB)        // 32768 (t,b) pairs
#define KPAD 832            // 784 padded to 13*64
#define NCH  13             // gemm1 K chunks of 64
#define NCH2 8              // gemm2 K chunks of 64 (512/64)
#define MTILES (MM/128)     // 256

// CUBA constants (exactly fp32-rounded like JAX)
#define C_A ((float)(1e-6*(1.0/6e-6)))           // 0.16666667f
#define C_D ((float)(1.0 - 1e-6*(1.0/6e-6)))     // 0.8333333f

// ---- scratch (device globals; no allocations allowed) ----
__device__ __half   g_a16 [(size_t)MM*KPAD];   // spikes fp16 K-padded    54.5 MB
__device__ __half   g_bhi [NHID*KPAD];         // w_hidden hi fp16        0.85 MB
__device__ __half   g_blo [NHID*KPAD];         // w_hidden lo fp16        0.85 MB
__device__ __half   g_ohi [NOUT*NHID];         // w_out hi fp16           128 KB
__device__ __half   g_olo [NOUT*NHID];         // w_out lo fp16           128 KB
__device__ float    g_ch  [(size_t)MM*NHID];   // hidden synaptic input   67 MB
__device__ __half   g_sh  [(size_t)MM*NHID];   // hidden spikes fp16      33.5 MB
__device__ float    g_co  [MM*NOUT];           // output synaptic input   16.8 MB

// ================= PTX helpers =================
__device__ __forceinline__ uint32_t smem_u32(const void* p) {
    uint32_t a;
    asm("{ .reg .u64 t; cvta.to.shared.u64 t, %1; cvt.u32.u64 %0, t; }" : "=r"(a) : "l"(p));
    return a;
}
#define CP_ASYNC16(dst, src) \
    asm volatile("cp.async.cg.shared.global [%0], [%1], 16;" :: "r"(dst), "l"(src))
#define CP_COMMIT()  asm volatile("cp.async.commit_group;" ::: "memory")
#define CP_WAIT(n)   asm volatile("cp.async.wait_group %0;" :: "n"(n) : "memory")

#define LDSM_X4(r0,r1,r2,r3, a) \
    asm volatile("ldmatrix.sync.aligned.m8n8.x4.shared.b16 {%0,%1,%2,%3}, [%4];" \
        : "=r"(r0),"=r"(r1),"=r"(r2),"=r"(r3) : "r"(a))
#define MMA16816(d, a0,a1,a2,a3, b0,b1) \
    asm volatile("mma.sync.aligned.m16n8k16.row.col.f32.f16.f16.f32 " \
        "{%0,%1,%2,%3}, {%4,%5,%6,%7}, {%8,%9}, {%0,%1,%2,%3};" \
        : "+f"((d)[0]),"+f"((d)[1]),"+f"((d)[2]),"+f"((d)[3]) \
        : "r"(a0),"r"(a1),"r"(a2),"r"(a3),"r"(b0),"r"(b1))

#define SWZ(off) ((off) ^ (((off) >> 3) & 0x70))

// ================= conversion kernels =================
// spikes fp32 [MM][784] -> fp16 [MM][832]. One thread per 16B output group.
// 832/8 = 104 groups per row; NIN/8 = 98 exactly, so groups 98..103 are pure zero.
#define AGRP 104
__global__ void k_a16(const float* __restrict__ spikes) {
    int idx = blockIdx.x*blockDim.x + threadIdx.x;
    if (idx >= MM*AGRP) return;
    int m = idx / AGRP, grp = idx - m*AGRP;
    uint4 out;
    if (grp < 98) {
        const float4* src = (const float4*)(spikes + (size_t)m*NIN + grp*8);
        float4 v0 = src[0];
        float4 v1 = src[1];
        __half2 h0 = __floats2half2_rn(v0.x, v0.y);
        __half2 h1 = __floats2half2_rn(v0.z, v0.w);
        __half2 h2 = __floats2half2_rn(v1.x, v1.y);
        __half2 h3 = __floats2half2_rn(v1.z, v1.w);
        out.x = *(uint32_t*)&h0; out.y = *(uint32_t*)&h1;
        out.z = *(uint32_t*)&h2; out.w = *(uint32_t*)&h3;
    } else {
        out.x = out.y = out.z = out.w = 0u;
    }
    *(uint4*)(g_a16 + (size_t)m*KPAD + grp*8) = out;
}

// combined weight split: w_hidden -> g_bhi/g_blo, w_out -> g_ohi/g_olo
__global__ void k_wsplit(const float* __restrict__ wh, const float* __restrict__ wo) {
    int idx = blockIdx.x*blockDim.x + threadIdx.x;
    if (idx < NHID*KPAD) {
        int h = idx / KPAD, k = idx - h*KPAD;
        __half hi = __float2half_rn(0.f), lo = __float2half_rn(0.f);
        if (k < NIN) {
            float wv = wh[h*NIN + k];
            hi = __float2half_rn(wv);
            lo = __float2half_rn(wv - __half2float(hi));
        }
        g_bhi[idx] = hi;
        g_blo[idx] = lo;
    } else {
        int j = idx - NHID*KPAD;
        if (j < NOUT*NHID) {
            float wv = wo[j];
            __half hi = __float2half_rn(wv);
            g_ohi[j] = hi;
            g_olo[j] = __float2half_rn(wv - __half2float(hi));
        }
    }
}

// ================= GEMM1 (frozen R6 core): warp tile 32x64, warps 4(m) x 2(n) =================
#define STAGE_BYTES 49152

__global__ void __launch_bounds__(256, 2) k_gemm1tc() {
    extern __shared__ char smem[];
    const int tid    = threadIdx.x;
    const int wid    = tid >> 5;
    const int lane   = tid & 31;
    const int warp_m = wid >> 1;
    const int warp_n = wid &  1;
    const int m_base = blockIdx.x * 128;
    const int n_base = blockIdx.y * 128;

    const uint32_t sbase = smem_u32(smem);

    auto load_tile = [&](int kc, int s) {
        const uint32_t st = sbase + s * STAGE_BYTES;
        const int kcol = kc * 64;
        #pragma unroll
        for (int it = 0; it < 4; it++) {
            int g = it * 256 + tid;
            int row = g >> 3, sub = g & 7;
            uint32_t off = row * 128 + sub * 16;
            const char* src = (const char*)(g_a16 + (size_t)(m_base + row)*KPAD + kcol) + sub*16;
            CP_ASYNC16(st + SWZ(off), src);
        }
        #pragma unroll
        for (int it = 0; it < 4; it++) {
            int g = it * 256 + tid;
            int row = g >> 3, sub = g & 7;
            uint32_t off = row * 128 + sub * 16;
            const char* srch = (const char*)(g_bhi + (size_t)(n_base + row)*KPAD + kcol) + sub*16;
            const char* srcl = (const char*)(g_blo + (size_t)(n_base + row)*KPAD + kcol) + sub*16;
            CP_ASYNC16(st + 16384 + SWZ(off), srch);
            CP_ASYNC16(st + 32768 + SWZ(off), srcl);
        }
        CP_COMMIT();
    };

    float acc[2][8][4];
    #pragma unroll
    for (int i = 0; i < 2; i++)
        #pragma unroll
        for (int j = 0; j < 8; j++)
            #pragma unroll
            for (int q = 0; q < 4; q++) acc[i][j][q] = 0.f;

    load_tile(0, 0);

    const int lrow = lane & 15, lcol = (lane >> 4) * 16;

    #pragma unroll 1
    for (int c = 0; c < NCH; c++) {
        const int buf = c & 1;
        if (c + 1 < NCH) { load_tile(c + 1, buf ^ 1); CP_WAIT(1); }
        else            { CP_WAIT(0); }
        __syncthreads();

        const uint32_t sA = sbase + buf * STAGE_BYTES;
        const uint32_t sBh = sA + 16384;
        const uint32_t sBl = sA + 32768;

        #pragma unroll
        for (int ks = 0; ks < 4; ks++) {
            uint32_t a[2][4], bh[4][4], bl[4][4];
            #pragma unroll
            for (int mt = 0; mt < 2; mt++) {
                uint32_t off = (uint32_t)(warp_m*32 + mt*16 + lrow)*128 + ks*32 + lcol;
                LDSM_X4(a[mt][0], a[mt][1], a[mt][2], a[mt][3], sA + SWZ(off));
            }
            #pragma unroll
            for (int nt = 0; nt < 4; nt++) {
                uint32_t off = (uint32_t)(warp_n*64 + nt*16 + lrow)*128 + ks*32 + lcol;
                uint32_t so = SWZ(off);
                LDSM_X4(bh[nt][0], bh[nt][1], bh[nt][2], bh[nt][3], sBh + so);
                LDSM_X4(bl[nt][0], bl[nt][1], bl[nt][2], bl[nt][3], sBl + so);
            }
            #pragma unroll
            for (int mt = 0; mt < 2; mt++)
                #pragma unroll
                for (int nt = 0; nt < 4; nt++) {
                    MMA16816(acc[mt][nt*2+0], a[mt][0],a[mt][1],a[mt][2],a[mt][3],
                             bh[nt][0], bh[nt][2]);
                    MMA16816(acc[mt][nt*2+1], a[mt][0],a[mt][1],a[mt][2],a[mt][3],
                             bh[nt][1], bh[nt][3]);
                    MMA16816(acc[mt][nt*2+0], a[mt][0],a[mt][1],a[mt][2],a[mt][3],
                             bl[nt][0], bl[nt][2]);
                    MMA16816(acc[mt][nt*2+1], a[mt][0],a[mt][1],a[mt][2],a[mt][3],
                             bl[nt][1], bl[nt][3]);
                }
        }
        __syncthreads();
    }

    const int erow = lane >> 2, ecol = (lane & 3) * 2;
    #pragma unroll
    for (int mt = 0; mt < 2; mt++) {
        #pragma unroll
        for (int nt = 0; nt < 8; nt++) {
            int col = n_base + warp_n*64 + nt*8 + ecol;
            int r0  = m_base + warp_m*32 + mt*16 + erow;
            float2 v0; v0.x = acc[mt][nt][0]; v0.y = acc[mt][nt][1];
            float2 v1; v1.x = acc[mt][nt][2]; v1.y = acc[mt][nt][3];
            *(float2*)(g_ch + (size_t)r0*NHID + col)       = v0;
            *(float2*)(g_ch + (size_t)(r0 + 8)*NHID + col) = v1;
        }
    }
}

// ================= GEMM2 (frozen R6 core): K=512, N=128 =================
__global__ void __launch_bounds__(256, 2) k_gemm2tc() {
    extern __shared__ char smem[];
    const int tid    = threadIdx.x;
    const int wid    = tid >> 5;
    const int lane   = tid & 31;
    const int warp_m = wid >> 1;
    const int warp_n = wid &  1;
    const int m_base = blockIdx.x * 128;

    const uint32_t sbase = smem_u32(smem);

    auto load_tile = [&](int kc, int s) {
        const uint32_t st = sbase + s * STAGE_BYTES;
        const int kcol = kc * 64;
        #pragma unroll
        for (int it = 0; it < 4; it++) {
            int g = it * 256 + tid;
            int row = g >> 3, sub = g & 7;
            uint32_t off = row * 128 + sub * 16;
            const char* src = (const char*)(g_sh + (size_t)(m_base + row)*NHID + kcol) + sub*16;
            CP_ASYNC16(st + SWZ(off), src);
        }
        #pragma unroll
        for (int it = 0; it < 4; it++) {
            int g = it * 256 + tid;
            int row = g >> 3, sub = g & 7;
            uint32_t off = row * 128 + sub * 16;
            const char* srch = (const char*)(g_ohi + (size_t)row*NHID + kcol) + sub*16;
            const char* srcl = (const char*)(g_olo + (size_t)row*NHID + kcol) + sub*16;
            CP_ASYNC16(st + 16384 + SWZ(off), srch);
            CP_ASYNC16(st + 32768 + SWZ(off), srcl);
        }
        CP_COMMIT();
    };

    float acc[2][8][4];
    #pragma unroll
    for (int i = 0; i < 2; i++)
        #pragma unroll
        for (int j = 0; j < 8; j++)
            #pragma unroll
            for (int q = 0; q < 4; q++) acc[i][j][q] = 0.f;

    load_tile(0, 0);

    const int lrow = lane & 15, lcol = (lane >> 4) * 16;

    #pragma unroll 1
    for (int c = 0; c < NCH2; c++) {
        const int buf = c & 1;
        if (c + 1 < NCH2) { load_tile(c + 1, buf ^ 1); CP_WAIT(1); }
        else             { CP_WAIT(0); }
        __syncthreads();

        const uint32_t sA = sbase + buf * STAGE_BYTES;
        const uint32_t sBh = sA + 16384;
        const uint32_t sBl = sA + 32768;

        #pragma unroll
        for (int ks = 0; ks < 4; ks++) {
            uint32_t a[2][4], bh[4][4], bl[4][4];
            #pragma unroll
            for (int mt = 0; mt < 2; mt++) {
                uint32_t off = (uint32_t)(warp_m*32 + mt*16 + lrow)*128 + ks*32 + lcol;
                LDSM_X4(a[mt][0], a[mt][1], a[mt][2], a[mt][3], sA + SWZ(off));
            }
            #pragma unroll
            for (int nt = 0; nt < 4; nt++) {
                uint32_t off = (uint32_t)(warp_n*64 + nt*16 + lrow)*128 + ks*32 + lcol;
                uint32_t so = SWZ(off);
                LDSM_X4(bh[nt][0], bh[nt][1], bh[nt][2], bh[nt][3], sBh + so);
                LDSM_X4(bl[nt][0], bl[nt][1], bl[nt][2], bl[nt][3], sBl + so);
            }
            #pragma unroll
            for (int mt = 0; mt < 2; mt++)
                #pragma unroll
                for (int nt = 0; nt < 4; nt++) {
                    MMA16816(acc[mt][nt*2+0], a[mt][0],a[mt][1],a[mt][2],a[mt][3],
                             bh[nt][0], bh[nt][2]);
                    MMA16816(acc[mt][nt*2+1], a[mt][0],a[mt][1],a[mt][2],a[mt][3],
                             bh[nt][1], bh[nt][3]);
                    MMA16816(acc[mt][nt*2+0], a[mt][0],a[mt][1],a[mt][2],a[mt][3],
                             bl[nt][0], bl[nt][2]);
                    MMA16816(acc[mt][nt*2+1], a[mt][0],a[mt][1],a[mt][2],a[mt][3],
                             bl[nt][1], bl[nt][3]);
                }
        }
        __syncthreads();
    }

    const int erow = lane >> 2, ecol = (lane & 3) * 2;
    #pragma unroll
    for (int mt = 0; mt < 2; mt++) {
        #pragma unroll
        for (int nt = 0; nt < 8; nt++) {
            int col = warp_n*64 + nt*8 + ecol;
            int r0  = m_base + warp_m*32 + mt*16 + erow;
            float2 v0; v0.x = acc[mt][nt][0]; v0.y = acc[mt][nt][1];
            float2 v1; v1.x = acc[mt][nt][2]; v1.y = acc[mt][nt][3];
            *(float2*)(g_co + (size_t)r0*NOUT + col)       = v0;
            *(float2*)(g_co + (size_t)(r0 + 8)*NOUT + col) = v1;
        }
    }
}

// ================= LIF scan: float2-wide, prefetch 16 (128B/thread in flight) =================
__global__ void k_lif() {
    int g2 = blockIdx.x*blockDim.x + threadIdx.x;   // pair index: 0 .. BB*NHID/2-1
    const float2* src = ((const float2*)g_ch) + g2;
    __half2*      dst = ((__half2*)g_sh) + g2;
    const int STRIDE2 = BB*NHID/2;                  // 32768 float2 per timestep
    float vx = 0.f, vy = 0.f, cx = 0.f, cy = 0.f;
    float2 xs[16];
    #pragma unroll
    for (int p = 0; p < 16; p++) xs[p] = __ldcs(src + (size_t)p*STRIDE2);
    #pragma unroll 1
    for (int t0 = 0; t0 < TT; t0 += 16) {
        #pragma unroll
        for (int p = 0; p < 16; p++) {
            float2 x = xs[p];
            int tn = t0 + 16 + p;
            if (tn < TT) xs[p] = __ldcs(src + (size_t)tn*STRIDE2);
            vx = vx + C_A*(cx - vx);
            vy = vy + C_A*(cy - vy);
            cx = cx*C_D + x.x;
            cy = cy*C_D + x.y;
            bool zx = vx > 1.0f, zy = vy > 1.0f;
            if (zx) vx = 0.f;
            if (zy) vy = 0.f;
            dst[(size_t)(t0 + p)*STRIDE2] = __floats2half2_rn(zx ? 1.f : 0.f,
                                                              zy ? 1.f : 0.f);
        }
    }
}

// ================= LI scan (prefetch 32, streaming loads + streaming stores) =================
__global__ void k_li(float* __restrict__ out) {
    int gid = blockIdx.x*blockDim.x + threadIdx.x;   // b*128 + o
    float v = 0.0f, cur = 0.0f;
    float xs[32];
    #pragma unroll
    for (int p = 0; p < 32; p++) xs[p] = __ldcs(g_co + p*(BB*NOUT) + gid);
    #pragma unroll 1
    for (int t0 = 0; t0 < TT; t0 += 32) {
        #pragma unroll
        for (int p = 0; p < 32; p++) {
            float x = xs[p];
            int tn = t0 + 32 + p;
            if (tn < TT) xs[p] = __ldcs(g_co + tn*(BB*NOUT) + gid);
            v   = v + C_A*(cur - v);
            cur = cur*C_D + x;
            __stcs(out + (t0 + p)*(BB*NOUT) + gid, v);
        }
    }
}

// ================= launch =================
extern "C" void kernel_launch(void* const* d_in, const int* in_sizes, int n_in,
                              void* d_out, int out_size) {
    const float *spikes = nullptr, *wh = nullptr, *wo = nullptr;
    for (int i = 0; i < n_in; i++) {
        if      (in_sizes[i] == TT*BB*NIN) spikes = (const float*)d_in[i];
        else if (in_sizes[i] == NHID*NIN)  wh     = (const float*)d_in[i];
        else if (in_sizes[i] == NOUT*NHID) wo     = (const float*)d_in[i];
    }
    cudaFuncSetAttribute(k_gemm1tc, cudaFuncAttributeMaxDynamicSharedMemorySize,
                         2*STAGE_BYTES);
    cudaFuncSetAttribute(k_gemm2tc, cudaFuncAttributeMaxDynamicSharedMemorySize,
                         2*STAGE_BYTES);
    k_wsplit <<<(NHID*KPAD + NOUT*NHID + 255)/256, 256>>>(wh, wo);
    k_a16    <<<(MM*AGRP + 255)/256, 256>>>(spikes);
    k_gemm1tc<<<dim3(MTILES, NHID/128), 256, 2*STAGE_BYTES>>>();
    k_lif    <<<(BB*NHID/2)/256, 256>>>();
    k_gemm2tc<<<MTILES, 256, 2*STAGE_BYTES>>>();
    k_li     <<<(BB*NOUT)/256, 256>>>((float*)d_out);
}

// round 12
// speedup vs baseline: 1.1505x; 1.0131x over previous
#include <cuda_runtime.h>
#include <cuda_fp16.h>
#include <stdint.h>

// Problem constants
#define TT   256
#define BB   128
#define NIN  784
#define NHID 512
#define NOUT 128
#define MM   (TT*BB)        // 32768 (t,b) pairs
#define KPAD 832            // 784 padded to 13*64
#define NCH  13             // gemm1 K chunks of 64
#define NCH2 8              // gemm2 K chunks of 64 (512/64)
#define MTILES (MM/128)     // 256

// CUBA constants (exactly fp32-rounded like JAX)
#define C_A ((float)(1e-6*(1.0/6e-6)))           // 0.16666667f
#define C_D ((float)(1.0 - 1e-6*(1.0/6e-6)))     // 0.8333333f

// ---- scratch (device globals; no allocations allowed) ----
__device__ __half   g_a16 [(size_t)MM*KPAD];   // spikes fp16 K-padded    54.5 MB
__device__ __half   g_bhi [NHID*KPAD];         // w_hidden hi fp16        0.85 MB
__device__ __half   g_blo [NHID*KPAD];         // w_hidden lo fp16        0.85 MB
__device__ __half   g_ohi [NOUT*NHID];         // w_out hi fp16           128 KB
__device__ __half   g_olo [NOUT*NHID];         // w_out lo fp16           128 KB
__device__ float    g_ch  [(size_t)MM*NHID];   // hidden synaptic input   67 MB
__device__ __half   g_sh  [(size_t)MM*NHID];   // hidden spikes fp16      33.5 MB
__device__ float    g_co  [MM*NOUT];           // output synaptic input   16.8 MB

// ================= PTX helpers =================
__device__ __forceinline__ uint32_t smem_u32(const void* p) {
    uint32_t a;
    asm("{ .reg .u64 t; cvta.to.shared.u64 t, %1; cvt.u32.u64 %0, t; }" : "=r"(a) : "l"(p));
    return a;
}
#define CP_ASYNC16(dst, src) \
    asm volatile("cp.async.cg.shared.global [%0], [%1], 16;" :: "r"(dst), "l"(src))
#define CP_COMMIT()  asm volatile("cp.async.commit_group;" ::: "memory")
#define CP_WAIT(n)   asm volatile("cp.async.wait_group %0;" :: "n"(n) : "memory")

#define LDSM_X4(r0,r1,r2,r3, a) \
    asm volatile("ldmatrix.sync.aligned.m8n8.x4.shared.b16 {%0,%1,%2,%3}, [%4];" \
        : "=r"(r0),"=r"(r1),"=r"(r2),"=r"(r3) : "r"(a))
#define MMA16816(d, a0,a1,a2,a3, b0,b1) \
    asm volatile("mma.sync.aligned.m16n8k16.row.col.f32.f16.f16.f32 " \
        "{%0,%1,%2,%3}, {%4,%5,%6,%7}, {%8,%9}, {%0,%1,%2,%3};" \
        : "+f"((d)[0]),"+f"((d)[1]),"+f"((d)[2]),"+f"((d)[3]) \
        : "r"(a0),"r"(a1),"r"(a2),"r"(a3),"r"(b0),"r"(b1))

#define SWZ(off) ((off) ^ (((off) >> 3) & 0x70))

// ================= prep kernel: A conversion + weight splits, fused =================
// Part 1 (blocks [0, A16_BLOCKS)): spikes fp32 [MM][784] -> fp16 [MM][832].
//   One thread per 16B output group; 832/8=104 groups/row, first 98 carry data.
// Part 2 (blocks after): w_hidden -> g_bhi/g_blo, w_out -> g_ohi/g_olo.
#define AGRP 104
#define A16_BLOCKS ((MM*AGRP + 255)/256)
#define WS_ELEMS   (NHID*KPAD + NOUT*NHID)
#define WS_BLOCKS  ((WS_ELEMS + 255)/256)

__global__ void k_prep(const float* __restrict__ spikes,
                       const float* __restrict__ wh,
                       const float* __restrict__ wo) {
    if (blockIdx.x < A16_BLOCKS) {
        int idx = blockIdx.x*blockDim.x + threadIdx.x;
        if (idx >= MM*AGRP) return;
        int m = idx / AGRP, grp = idx - m*AGRP;
        uint4 out;
        if (grp < 98) {
            const float4* src = (const float4*)(spikes + (size_t)m*NIN + grp*8);
            float4 v0 = __ldcs(src);
            float4 v1 = __ldcs(src + 1);
            __half2 h0 = __floats2half2_rn(v0.x, v0.y);
            __half2 h1 = __floats2half2_rn(v0.z, v0.w);
            __half2 h2 = __floats2half2_rn(v1.x, v1.y);
            __half2 h3 = __floats2half2_rn(v1.z, v1.w);
            out.x = *(uint32_t*)&h0; out.y = *(uint32_t*)&h1;
            out.z = *(uint32_t*)&h2; out.w = *(uint32_t*)&h3;
        } else {
            out.x = out.y = out.z = out.w = 0u;
        }
        __stcs((uint4*)(g_a16 + (size_t)m*KPAD + grp*8), out);
    } else {
        int idx = (blockIdx.x - A16_BLOCKS)*blockDim.x + threadIdx.x;
        if (idx < NHID*KPAD) {
            int h = idx / KPAD, k = idx - h*KPAD;
            __half hi = __float2half_rn(0.f), lo = __float2half_rn(0.f);
            if (k < NIN) {
                float wv = wh[h*NIN + k];
                hi = __float2half_rn(wv);
                lo = __float2half_rn(wv - __half2float(hi));
            }
            g_bhi[idx] = hi;
            g_blo[idx] = lo;
        } else {
            int j = idx - NHID*KPAD;
            if (j < NOUT*NHID) {
                float wv = wo[j];
                __half hi = __float2half_rn(wv);
                g_ohi[j] = hi;
                g_olo[j] = __float2half_rn(wv - __half2float(hi));
            }
        }
    }
}

// ================= GEMM1 (frozen R6 core): warp tile 32x64, warps 4(m) x 2(n) =================
#define STAGE_BYTES 49152

__global__ void __launch_bounds__(256, 2) k_gemm1tc() {
    extern __shared__ char smem[];
    const int tid    = threadIdx.x;
    const int wid    = tid >> 5;
    const int lane   = tid & 31;
    const int warp_m = wid >> 1;
    const int warp_n = wid &  1;
    const int m_base = blockIdx.x * 128;
    const int n_base = blockIdx.y * 128;

    const uint32_t sbase = smem_u32(smem);

    auto load_tile = [&](int kc, int s) {
        const uint32_t st = sbase + s * STAGE_BYTES;
        const int kcol = kc * 64;
        #pragma unroll
        for (int it = 0; it < 4; it++) {
            int g = it * 256 + tid;
            int row = g >> 3, sub = g & 7;
            uint32_t off = row * 128 + sub * 16;
            const char* src = (const char*)(g_a16 + (size_t)(m_base + row)*KPAD + kcol) + sub*16;
            CP_ASYNC16(st + SWZ(off), src);
        }
        #pragma unroll
        for (int it = 0; it < 4; it++) {
            int g = it * 256 + tid;
            int row = g >> 3, sub = g & 7;
            uint32_t off = row * 128 + sub * 16;
            const char* srch = (const char*)(g_bhi + (size_t)(n_base + row)*KPAD + kcol) + sub*16;
            const char* srcl = (const char*)(g_blo + (size_t)(n_base + row)*KPAD + kcol) + sub*16;
            CP_ASYNC16(st + 16384 + SWZ(off), srch);
            CP_ASYNC16(st + 32768 + SWZ(off), srcl);
        }
        CP_COMMIT();
    };

    float acc[2][8][4];
    #pragma unroll
    for (int i = 0; i < 2; i++)
        #pragma unroll
        for (int j = 0; j < 8; j++)
            #pragma unroll
            for (int q = 0; q < 4; q++) acc[i][j][q] = 0.f;

    load_tile(0, 0);

    const int lrow = lane & 15, lcol = (lane >> 4) * 16;

    #pragma unroll 1
    for (int c = 0; c < NCH; c++) {
        const int buf = c & 1;
        if (c + 1 < NCH) { load_tile(c + 1, buf ^ 1); CP_WAIT(1); }
        else            { CP_WAIT(0); }
        __syncthreads();

        const uint32_t sA = sbase + buf * STAGE_BYTES;
        const uint32_t sBh = sA + 16384;
        const uint32_t sBl = sA + 32768;

        #pragma unroll
        for (int ks = 0; ks < 4; ks++) {
            uint32_t a[2][4], bh[4][4], bl[4][4];
            #pragma unroll
            for (int mt = 0; mt < 2; mt++) {
                uint32_t off = (uint32_t)(warp_m*32 + mt*16 + lrow)*128 + ks*32 + lcol;
                LDSM_X4(a[mt][0], a[mt][1], a[mt][2], a[mt][3], sA + SWZ(off));
            }
            #pragma unroll
            for (int nt = 0; nt < 4; nt++) {
                uint32_t off = (uint32_t)(warp_n*64 + nt*16 + lrow)*128 + ks*32 + lcol;
                uint32_t so = SWZ(off);
                LDSM_X4(bh[nt][0], bh[nt][1], bh[nt][2], bh[nt][3], sBh + so);
                LDSM_X4(bl[nt][0], bl[nt][1], bl[nt][2], bl[nt][3], sBl + so);
            }
            #pragma unroll
            for (int mt = 0; mt < 2; mt++)
                #pragma unroll
                for (int nt = 0; nt < 4; nt++) {
                    MMA16816(acc[mt][nt*2+0], a[mt][0],a[mt][1],a[mt][2],a[mt][3],
                             bh[nt][0], bh[nt][2]);
                    MMA16816(acc[mt][nt*2+1], a[mt][0],a[mt][1],a[mt][2],a[mt][3],
                             bh[nt][1], bh[nt][3]);
                    MMA16816(acc[mt][nt*2+0], a[mt][0],a[mt][1],a[mt][2],a[mt][3],
                             bl[nt][0], bl[nt][2]);
                    MMA16816(acc[mt][nt*2+1], a[mt][0],a[mt][1],a[mt][2],a[mt][3],
                             bl[nt][1], bl[nt][3]);
                }
        }
        __syncthreads();
    }

    const int erow = lane >> 2, ecol = (lane & 3) * 2;
    #pragma unroll
    for (int mt = 0; mt < 2; mt++) {
        #pragma unroll
        for (int nt = 0; nt < 8; nt++) {
            int col = n_base + warp_n*64 + nt*8 + ecol;
            int r0  = m_base + warp_m*32 + mt*16 + erow;
            float2 v0; v0.x = acc[mt][nt][0]; v0.y = acc[mt][nt][1];
            float2 v1; v1.x = acc[mt][nt][2]; v1.y = acc[mt][nt][3];
            *(float2*)(g_ch + (size_t)r0*NHID + col)       = v0;
            *(float2*)(g_ch + (size_t)(r0 + 8)*NHID + col) = v1;
        }
    }
}

// ================= GEMM2 (frozen R6 core): K=512, N=128 =================
__global__ void __launch_bounds__(256, 2) k_gemm2tc() {
    extern __shared__ char smem[];
    const int tid    = threadIdx.x;
    const int wid    = tid >> 5;
    const int lane   = tid & 31;
    const int warp_m = wid >> 1;
    const int warp_n = wid &  1;
    const int m_base = blockIdx.x * 128;

    const uint32_t sbase = smem_u32(smem);

    auto load_tile = [&](int kc, int s) {
        const uint32_t st = sbase + s * STAGE_BYTES;
        const int kcol = kc * 64;
        #pragma unroll
        for (int it = 0; it < 4; it++) {
            int g = it * 256 + tid;
            int row = g >> 3, sub = g & 7;
            uint32_t off = row * 128 + sub * 16;
            const char* src = (const char*)(g_sh + (size_t)(m_base + row)*NHID + kcol) + sub*16;
            CP_ASYNC16(st + SWZ(off), src);
        }
        #pragma unroll
        for (int it = 0; it < 4; it++) {
            int g = it * 256 + tid;
            int row = g >> 3, sub = g & 7;
            uint32_t off = row * 128 + sub * 16;
            const char* srch = (const char*)(g_ohi + (size_t)row*NHID + kcol) + sub*16;
            const char* srcl = (const char*)(g_olo + (size_t)row*NHID + kcol) + sub*16;
            CP_ASYNC16(st + 16384 + SWZ(off), srch);
            CP_ASYNC16(st + 32768 + SWZ(off), srcl);
        }
        CP_COMMIT();
    };

    float acc[2][8][4];
    #pragma unroll
    for (int i = 0; i < 2; i++)
        #pragma unroll
        for (int j = 0; j < 8; j++)
            #pragma unroll
            for (int q = 0; q < 4; q++) acc[i][j][q] = 0.f;

    load_tile(0, 0);

    const int lrow = lane & 15, lcol = (lane >> 4) * 16;

    #pragma unroll 1
    for (int c = 0; c < NCH2; c++) {
        const int buf = c & 1;
        if (c + 1 < NCH2) { load_tile(c + 1, buf ^ 1); CP_WAIT(1); }
        else             { CP_WAIT(0); }
        __syncthreads();

        const uint32_t sA = sbase + buf * STAGE_BYTES;
        const uint32_t sBh = sA + 16384;
        const uint32_t sBl = sA + 32768;

        #pragma unroll
        for (int ks = 0; ks < 4; ks++) {
            uint32_t a[2][4], bh[4][4], bl[4][4];
            #pragma unroll
            for (int mt = 0; mt < 2; mt++) {
                uint32_t off = (uint32_t)(warp_m*32 + mt*16 + lrow)*128 + ks*32 + lcol;
                LDSM_X4(a[mt][0], a[mt][1], a[mt][2], a[mt][3], sA + SWZ(off));
            }
            #pragma unroll
            for (int nt = 0; nt < 4; nt++) {
                uint32_t off = (uint32_t)(warp_n*64 + nt*16 + lrow)*128 + ks*32 + lcol;
                uint32_t so = SWZ(off);
                LDSM_X4(bh[nt][0], bh[nt][1], bh[nt][2], bh[nt][3], sBh + so);
                LDSM_X4(bl[nt][0], bl[nt][1], bl[nt][2], bl[nt][3], sBl + so);
            }
            #pragma unroll
            for (int mt = 0; mt < 2; mt++)
                #pragma unroll
                for (int nt = 0; nt < 4; nt++) {
                    MMA16816(acc[mt][nt*2+0], a[mt][0],a[mt][1],a[mt][2],a[mt][3],
                             bh[nt][0], bh[nt][2]);
                    MMA16816(acc[mt][nt*2+1], a[mt][0],a[mt][1],a[mt][2],a[mt][3],
                             bh[nt][1], bh[nt][3]);
                    MMA16816(acc[mt][nt*2+0], a[mt][0],a[mt][1],a[mt][2],a[mt][3],
                             bl[nt][0], bl[nt][2]);
                    MMA16816(acc[mt][nt*2+1], a[mt][0],a[mt][1],a[mt][2],a[mt][3],
                             bl[nt][1], bl[nt][3]);
                }
        }
        __syncthreads();
    }

    const int erow = lane >> 2, ecol = (lane & 3) * 2;
    #pragma unroll
    for (int mt = 0; mt < 2; mt++) {
        #pragma unroll
        for (int nt = 0; nt < 8; nt++) {
            int col = warp_n*64 + nt*8 + ecol;
            int r0  = m_base + warp_m*32 + mt*16 + erow;
            float2 v0; v0.x = acc[mt][nt][0]; v0.y = acc[mt][nt][1];
            float2 v1; v1.x = acc[mt][nt][2]; v1.y = acc[mt][nt][3];
            *(float2*)(g_co + (size_t)r0*NOUT + col)       = v0;
            *(float2*)(g_co + (size_t)(r0 + 8)*NOUT + col) = v1;
        }
    }
}

// ================= LIF scan: float2-wide, prefetch 16; 256 CTAs cover all SMs =================
__global__ void k_lif() {
    int g2 = blockIdx.x*blockDim.x + threadIdx.x;   // pair index: 0 .. BB*NHID/2-1
    const float2* src = ((const float2*)g_ch) + g2;
    __half2*      dst = ((__half2*)g_sh) + g2;
    const int STRIDE2 = BB*NHID/2;                  // 32768 float2 per timestep
    float vx = 0.f, vy = 0.f, cx = 0.f, cy = 0.f;
    float2 xs[16];
    #pragma unroll
    for (int p = 0; p < 16; p++) xs[p] = __ldcs(src + (size_t)p*STRIDE2);
    #pragma unroll 1
    for (int t0 = 0; t0 < TT; t0 += 16) {
        #pragma unroll
        for (int p = 0; p < 16; p++) {
            float2 x = xs[p];
            int tn = t0 + 16 + p;
            if (tn < TT) xs[p] = __ldcs(src + (size_t)tn*STRIDE2);
            vx = vx + C_A*(cx - vx);
            vy = vy + C_A*(cy - vy);
            cx = cx*C_D + x.x;
            cy = cy*C_D + x.y;
            bool zx = vx > 1.0f, zy = vy > 1.0f;
            if (zx) vx = 0.f;
            if (zy) vy = 0.f;
            dst[(size_t)(t0 + p)*STRIDE2] = __floats2half2_rn(zx ? 1.f : 0.f,
                                                              zy ? 1.f : 0.f);
        }
    }
}

// ================= LI scan (prefetch 32); 256 CTAs cover all SMs =================
__global__ void k_li(float* __restrict__ out) {
    int gid = blockIdx.x*blockDim.x + threadIdx.x;   // b*128 + o
    float v = 0.0f, cur = 0.0f;
    float xs[32];
    #pragma unroll
    for (int p = 0; p < 32; p++) xs[p] = __ldcs(g_co + p*(BB*NOUT) + gid);
    #pragma unroll 1
    for (int t0 = 0; t0 < TT; t0 += 32) {
        #pragma unroll
        for (int p = 0; p < 32; p++) {
            float x = xs[p];
            int tn = t0 + 32 + p;
            if (tn < TT) xs[p] = __ldcs(g_co + tn*(BB*NOUT) + gid);
            v   = v + C_A*(cur - v);
            cur = cur*C_D + x;
            __stcs(out + (t0 + p)*(BB*NOUT) + gid, v);
        }
    }
}

// ================= launch =================
extern "C" void kernel_launch(void* const* d_in, const int* in_sizes, int n_in,
                              void* d_out, int out_size) {
    const float *spikes = nullptr, *wh = nullptr, *wo = nullptr;
    for (int i = 0; i < n_in; i++) {
        if      (in_sizes[i] == TT*BB*NIN) spikes = (const float*)d_in[i];
        else if (in_sizes[i] == NHID*NIN)  wh     = (const float*)d_in[i];
        else if (in_sizes[i] == NOUT*NHID) wo     = (const float*)d_in[i];
    }
    cudaFuncSetAttribute(k_gemm1tc, cudaFuncAttributeMaxDynamicSharedMemorySize,
                         2*STAGE_BYTES);
    cudaFuncSetAttribute(k_gemm2tc, cudaFuncAttributeMaxDynamicSharedMemorySize,
                         2*STAGE_BYTES);
    k_prep   <<<A16_BLOCKS + WS_BLOCKS, 256>>>(spikes, wh, wo);
    k_gemm1tc<<<dim3(MTILES, NHID/128), 256, 2*STAGE_BYTES>>>();
    k_lif    <<<(BB*NHID/2)/128, 128>>>();
    k_gemm2tc<<<MTILES, 256, 2*STAGE_BYTES>>>();
    k_li     <<<(BB*NOUT)/64, 64>>>((float*)d_out);
}